// round 16
// baseline (speedup 1.0000x reference)
#include <cuda_runtime.h>
#include <cuda_fp16.h>
#include <cstdint>

#define H 512
#define W 512
#define HW (H*W)
#define NB 2
#define NC 21
#define NCC 11           // channel pairs (ch20 paired with zero pad)
#define NPIX (NB*HW)
#define NTAP 25
#define NBHW (NB*HW)
#define W2P 1032         // padded row: (W+4) px * 2 ch = floats per (y,cc) plane

// q buffers: x-PADDED pair-planar [b][y][cc][x+2][2] fp32 (pads hold x-reflect)
// coefs planar fp16 [tap][b][y][x]
__device__ float  g_qA[(size_t)NB*H*NCC*W2P];
__device__ float  g_qB[(size_t)NB*H*NCC*W2P];
__device__ __half g_wch[NTAP*NB*HW];

__device__ __forceinline__ int reflect_idx(int i, int n) {
    if (i < 0) i = -i;
    if (i >= n) i = 2*n - 2 - i;
    return i;
}

__device__ __forceinline__ unsigned long long pk2(float lo, float hi) {
    unsigned long long r;
    asm("mov.b64 %0, {%1, %2};" : "=l"(r) : "f"(lo), "f"(hi));
    return r;
}
__device__ __forceinline__ void upk2(float& lo, float& hi, unsigned long long v) {
    asm("mov.b64 {%0, %1}, %2;" : "=f"(lo), "=f"(hi) : "l"(v));
}
#define FMA2(acc, a, b) \
    asm("fma.rn.f32x2 %0, %1, %2, %0;" : "+l"(acc) : "l"(a), "l"(b))
#define MUL2(out, a, b) \
    asm("mul.rn.f32x2 %0, %1, %2;" : "=l"(out) : "l"(a), "l"(b))

// streaming (evict-first) loads to protect L1 for the q working set
__device__ __forceinline__ uint32_t ldcs_u32(const void* p) {
    uint32_t v;
    asm("ld.global.cs.b32 %0, [%1];" : "=r"(v) : "l"(p));
    return v;
}
__device__ __forceinline__ float2 ldcs_f2(const float* p) {
    float2 v;
    asm("ld.global.cs.v2.f32 {%0, %1}, [%2];" : "=f"(v.x), "=f"(v.y) : "l"(p));
    return v;
}

// ---------------------------------------------------------------------------
// Kernel 1: q0 = softmax(unary), written padded pair-planar (incl. x pads)
// ---------------------------------------------------------------------------
__global__ void __launch_bounds__(256) init_softmax(const float* __restrict__ unary,
                                                    float* __restrict__ q) {
    int idx = blockIdx.x * 256 + threadIdx.x;
    if (idx >= NPIX) return;
    int b = idx / HW, pix = idx % HW;
    int y = pix / W, x = pix % W;
    const float* u = unary + (size_t)b * NC * HW + pix;
    float e[NC];
    float s = 0.f;
#pragma unroll
    for (int c = 0; c < NC; c++) { e[c] = __expf(u[c*HW]); s += e[c]; }
    float inv = 1.f / s;
    float* qrow = q + ((size_t)(b*H + y)*NCC)*W2P;
    int moff = (x + 2)*2;
    // x-reflect pad duplicates: pad[-1]=q[1], pad[-2]=q[2], pad[512]=q[510], pad[513]=q[509]
    int poff = -1;
    if      (x == 1)   poff = 2;      // p=-1 -> float off 2
    else if (x == 2)   poff = 0;      // p=-2 -> 0
    else if (x == 510) poff = 1028;   // p=512
    else if (x == 509) poff = 1030;   // p=513
#pragma unroll
    for (int cc = 0; cc < NCC; cc++) {
        float2 v;
        v.x = e[2*cc]*inv;
        v.y = (cc < 10) ? e[2*cc+1]*inv : 0.f;
        *reinterpret_cast<float2*>(qrow + cc*W2P + moff) = v;
        if (poff >= 0)
            *reinterpret_cast<float2*>(qrow + cc*W2P + poff) = v;
    }
}

// ---------------------------------------------------------------------------
// Kernel 2: combined coefficients (fp16, planar SoA [tap][b][y][x])
// ---------------------------------------------------------------------------
__global__ void __launch_bounds__(256) compute_weights(const float* __restrict__ image,
                                                       const float* __restrict__ edges) {
    __shared__ float sg[4][12][36];
    int tx = threadIdx.x, ty = threadIdx.y;
    int b = blockIdx.z;
    int x0 = blockIdx.x * 32, y0 = blockIdx.y * 8;
    int tid = ty * 32 + tx;

    for (int idx = tid; idx < 4*12*36; idx += 256) {
        int ch = idx / (12*36);
        int r  = idx % (12*36);
        int ry = r / 36, sx = r % 36;
        int gy = reflect_idx(y0 + ry - 2, H);
        int gx = reflect_idx(x0 + sx - 2, W);
        float v;
        if (ch < 3) v = image[((size_t)(b*3 + ch))*HW + gy*W + gx];
        else        v = edges[(size_t)b*HW + gy*W + gx];
        sg[ch][ry][sx] = v;
    }
    __syncthreads();

    float sp[5], g2[5];
    {
        float s = 0.f;
#pragma unroll
        for (int i = 0; i < 5; i++) {
            float x = (float)(i - 2);
            sp[i] = __expf(-x*x * 0.02f);
            float g = __expf(-2.f * x*x);
            g2[i] = g; s += g;
        }
        float inv = 1.f / s;
#pragma unroll
        for (int i = 0; i < 5; i++) g2[i] *= inv;
    }

    int ry = ty + 2, rx = tx + 2;
    float cr = sg[0][ry][rx], cg = sg[1][ry][rx], cb = sg[2][ry][rx], ce = sg[3][ry][rx];

    float wr[NTAP], we[NTAP];
    float sr = 0.f, se = 0.f;
#pragma unroll
    for (int dy = 0; dy < 5; dy++) {
#pragma unroll
        for (int dx = 0; dx < 5; dx++) {
            int t = dy*5 + dx;
            float d = fabsf(sg[0][ry+dy-2][rx+dx-2] - cr)
                    + fabsf(sg[1][ry+dy-2][rx+dx-2] - cg)
                    + fabsf(sg[2][ry+dy-2][rx+dx-2] - cb);
            float s2 = sp[dy] * sp[dx];
            float w  = s2 * __expf(-2.f * d * d);
            wr[t] = w; sr += w;
            float de = fabsf(sg[3][ry+dy-2][rx+dx-2] - ce);
            float w2 = s2 * __expf(-2.f * de * de);
            we[t] = w2; se += w2;
        }
    }
    float isr = 1.f / sr, ise = 1.f / se;
    int pix = b*HW + (y0 + ty)*W + (x0 + tx);
#pragma unroll
    for (int dy = 0; dy < 5; dy++) {
#pragma unroll
        for (int dx = 0; dx < 5; dx++) {
            int t = dy*5 + dx;
            g_wch[t*(NB*HW) + pix] = __float2half(g2[dy]*g2[dx] + wr[t]*isr + we[t]*ise);
        }
    }
}

// ---------------------------------------------------------------------------
// Kernel 3: one CRF iteration — NO SMEM. Stencil reads q straight from global
// through L1 (3 co-resident CTAs' windows ~210KB fit the 228KB L1).
// Tile 64x8, block (32,8)=256 thr, 2 px/thread, 3 CTAs/SM.
// Per (dy,cc): 3x LDG.128 (aligned; imm offsets off per-dy row ptr) + 10 FFMA2.
// x-reflect handled by padded q rows; y-reflect via 5 reflected row pointers.
// Coefs/unary loaded .cs (evict-first) to keep L1 for q.
// ---------------------------------------------------------------------------
#define TX 64
#define TY 8

template<bool FINAL>
__global__ void __launch_bounds__(256, 3) crf_iter(const float* __restrict__ unary,
                                                   const float* __restrict__ qin,
                                                   float* __restrict__ qout,
                                                   float* __restrict__ outp) {
    int tx = threadIdx.x, ty = threadIdx.y;
    int b = blockIdx.z;
    int x0 = blockIdx.x * TX, y0 = blockIdx.y * TY;

    int px0 = x0 + 2*tx;
    int gy  = y0 + ty;

    const float* qb = qin + (size_t)b * H * NCC * W2P;

    unsigned long long acc0[NCC], acc1[NCC];
#pragma unroll
    for (int cc = 0; cc < NCC; cc++) { acc0[cc] = 0ULL; acc1[cc] = 0ULL; }

    int wbase = b*HW + gy*W + px0;

#pragma unroll
    for (int dy = 0; dy < 5; dy++) {
        // coefs for this dy (fp16, streaming) -> broadcast fp32x2 pairs
        const __half* wp = g_wch + (size_t)(dy*5)*NBHW + wbase;
        uint32_t r0 = ldcs_u32(wp);
        uint32_t r1 = ldcs_u32(wp +   (size_t)NBHW);
        uint32_t r2 = ldcs_u32(wp + 2*(size_t)NBHW);
        uint32_t r3 = ldcs_u32(wp + 3*(size_t)NBHW);
        uint32_t r4 = ldcs_u32(wp + 4*(size_t)NBHW);
        float2 c0 = __half22float2(*reinterpret_cast<__half2*>(&r0));
        float2 c1 = __half22float2(*reinterpret_cast<__half2*>(&r1));
        float2 c2 = __half22float2(*reinterpret_cast<__half2*>(&r2));
        float2 c3 = __half22float2(*reinterpret_cast<__half2*>(&r3));
        float2 c4 = __half22float2(*reinterpret_cast<__half2*>(&r4));
        unsigned long long CC00 = pk2(c0.x, c0.x), CC10 = pk2(c0.y, c0.y);
        unsigned long long CC01 = pk2(c1.x, c1.x), CC11 = pk2(c1.y, c1.y);
        unsigned long long CC02 = pk2(c2.x, c2.x), CC12 = pk2(c2.y, c2.y);
        unsigned long long CC03 = pk2(c3.x, c3.x), CC13 = pk2(c3.y, c3.y);
        unsigned long long CC04 = pk2(c4.x, c4.x), CC14 = pk2(c4.y, c4.y);

        // reflected row pointer for this dy; window starts at px0-2
        int gyr = reflect_idx(gy + dy - 2, H);
        const float* row = qb + (size_t)gyr * (NCC*W2P) + px0*2;  // = pad-adjusted window base
#pragma unroll
        for (int cc = 0; cc < NCC; cc++) {
            const ulonglong2* a = reinterpret_cast<const ulonglong2*>(row + cc*W2P);
            ulonglong2 w01 = a[0];   // px cols 0,1 of window
            ulonglong2 w23 = a[1];   // cols 2,3
            ulonglong2 w45 = a[2];   // cols 4,5
            FMA2(acc0[cc], CC00, w01.x);
            FMA2(acc0[cc], CC01, w01.y);
            FMA2(acc0[cc], CC02, w23.x);
            FMA2(acc0[cc], CC03, w23.y);
            FMA2(acc0[cc], CC04, w45.x);
            FMA2(acc1[cc], CC10, w01.y);
            FMA2(acc1[cc], CC11, w23.x);
            FMA2(acc1[cc], CC12, w23.y);
            FMA2(acc1[cc], CC13, w45.x);
            FMA2(acc1[cc], CC14, w45.y);
        }
    }

    // ---- epilogue: q = softmax(unary - F) ----
    const float* ub = unary + (size_t)b * NC * HW + gy*W + px0;
    float s0 = 0.f, s1 = 0.f;
#pragma unroll
    for (int cc = 0; cc < NCC; cc++) {
        float fa, fb, ga, gb;
        upk2(fa, fb, acc0[cc]);   // px0: ch 2cc, 2cc+1
        upk2(ga, gb, acc1[cc]);   // px1
        float2 uA = ldcs_f2(ub + (size_t)(2*cc)*HW);
        float e00 = __expf(uA.x - fa);
        float e10 = __expf(uA.y - ga);
        float e01 = 0.f, e11 = 0.f;
        if (cc < 10) {
            float2 uB = ldcs_f2(ub + (size_t)(2*cc+1)*HW);
            e01 = __expf(uB.x - fb);
            e11 = __expf(uB.y - gb);
        }
        acc0[cc] = pk2(e00, e01);
        acc1[cc] = pk2(e10, e11);
        s0 += e00 + e01;
        s1 += e10 + e11;
    }
    float i0 = 1.f / s0, i1 = 1.f / s1;

    if (FINAL) {
        float* op = outp + (size_t)b * NC * HW + gy*W + px0;
#pragma unroll
        for (int cc = 0; cc < NCC; cc++) {
            float e00, e01, e10, e11;
            upk2(e00, e01, acc0[cc]);
            upk2(e10, e11, acc1[cc]);
            float2 vA; vA.x = e00*i0; vA.y = e10*i1;
            *reinterpret_cast<float2*>(op + (size_t)(2*cc)*HW) = vA;
            if (cc < 10) {
                float2 vB; vB.x = e01*i0; vB.y = e11*i1;
                *reinterpret_cast<float2*>(op + (size_t)(2*cc+1)*HW) = vB;
            }
        }
    } else {
        unsigned long long I0 = pk2(i0, i0), I1 = pk2(i1, i1);
        float* qrow = qout + (size_t)b * H * NCC * W2P + (size_t)gy * (NCC*W2P);
        int moff = (px0 + 2)*2;
        // pad duplicate: which pad (if any) this thread owns, and from which px
        int poff = -1; bool useY = false;
        if      (px0 == 0)   { poff = 2;    useY = true;  }  // q[1] -> pad[-1]
        else if (px0 == 2)   { poff = 0;    useY = false; }  // q[2] -> pad[-2]
        else if (px0 == 510) { poff = 1028; useY = false; }  // q[510] -> pad[512]
        else if (px0 == 508) { poff = 1030; useY = true;  }  // q[509] -> pad[513]
#pragma unroll
        for (int cc = 0; cc < NCC; cc++) {
            ulonglong2 st;
            MUL2(st.x, acc0[cc], I0);   // px0 pair
            MUL2(st.y, acc1[cc], I1);   // px1 pair
            *reinterpret_cast<ulonglong2*>(qrow + cc*W2P + moff) = st;
            if (poff >= 0) {
                *reinterpret_cast<unsigned long long*>(qrow + cc*W2P + poff) =
                    useY ? st.y : st.x;
            }
        }
    }
}

// ---------------------------------------------------------------------------
extern "C" void kernel_launch(void* const* d_in, const int* in_sizes, int n_in,
                              void* d_out, int out_size) {
    const float *unary = nullptr, *image = nullptr, *edges = nullptr;
    for (int i = 0; i < n_in; i++) {
        if      (in_sizes[i] == NB*NC*HW) unary = (const float*)d_in[i];
        else if (in_sizes[i] == NB*3*HW)  image = (const float*)d_in[i];
        else if (in_sizes[i] == NB*HW)    edges = (const float*)d_in[i];
    }
    float* out = (float*)d_out;

    float *qA = nullptr, *qB = nullptr;
    cudaGetSymbolAddress((void**)&qA, g_qA);
    cudaGetSymbolAddress((void**)&qB, g_qB);

    init_softmax<<<(NPIX + 255)/256, 256>>>(unary, qA);
    compute_weights<<<dim3(W/32, H/8, NB), dim3(32, 8)>>>(image, edges);

    dim3 gi(W/TX, H/TY, NB), bi(32, 8);
    const float* cur = qA;
    for (int it = 0; it < 9; it++) {
        float* dst = (cur == qA) ? qB : qA;
        crf_iter<false><<<gi, bi>>>(unary, cur, dst, nullptr);
        cur = dst;
    }
    crf_iter<true><<<gi, bi>>>(unary, cur, nullptr, out);
}

// round 17
// speedup vs baseline: 1.1387x; 1.1387x over previous
#include <cuda_runtime.h>
#include <cuda_fp16.h>
#include <cstdint>

#define H 512
#define W 512
#define HW (H*W)
#define NB 2
#define NC 21
#define NCC 11           // channel pairs (ch20 paired with zero pad)
#define NPIX (NB*HW)
#define NTAP 25
#define NBHW (NB*HW)

// q buffers: pair-planar layout [b][y][cc][x][2] fp32; coefs planar fp16
__device__ float  g_qA[(size_t)NB*H*NCC*W*2];
__device__ float  g_qB[(size_t)NB*H*NCC*W*2];
__device__ __half g_wch[NTAP*NB*HW];

__device__ __forceinline__ int reflect_idx(int i, int n) {
    if (i < 0) i = -i;
    if (i >= n) i = 2*n - 2 - i;
    return i;
}

__device__ __forceinline__ unsigned long long pk2(float lo, float hi) {
    unsigned long long r;
    asm("mov.b64 %0, {%1, %2};" : "=l"(r) : "f"(lo), "f"(hi));
    return r;
}
__device__ __forceinline__ void upk2(float& lo, float& hi, unsigned long long v) {
    asm("mov.b64 {%0, %1}, %2;" : "=f"(lo), "=f"(hi) : "l"(v));
}
#define FMA2(acc, a, b) \
    asm("fma.rn.f32x2 %0, %1, %2, %0;" : "+l"(acc) : "l"(a), "l"(b))
#define MUL2(out, a, b) \
    asm("mul.rn.f32x2 %0, %1, %2;" : "=l"(out) : "l"(a), "l"(b))

// ---------------------------------------------------------------------------
// Kernel 1: q0 = softmax(unary), written pair-planar
// ---------------------------------------------------------------------------
__global__ void __launch_bounds__(256) init_softmax(const float* __restrict__ unary,
                                                    float* __restrict__ q) {
    int idx = blockIdx.x * 256 + threadIdx.x;
    if (idx >= NPIX) return;
    int b = idx / HW, pix = idx % HW;
    int y = pix / W, x = pix % W;
    const float* u = unary + (size_t)b * NC * HW + pix;
    float e[NC];
    float s = 0.f;
#pragma unroll
    for (int c = 0; c < NC; c++) { e[c] = __expf(u[c*HW]); s += e[c]; }
    float inv = 1.f / s;
    float* qr = q + ((size_t)(b*H + y)*NCC)*(W*2) + x*2;
#pragma unroll
    for (int cc = 0; cc < 10; cc++) {
        float2 v; v.x = e[2*cc]*inv; v.y = e[2*cc+1]*inv;
        *reinterpret_cast<float2*>(qr + cc*(W*2)) = v;
    }
    float2 v10; v10.x = e[20]*inv; v10.y = 0.f;
    *reinterpret_cast<float2*>(qr + 10*(W*2)) = v10;
}

// ---------------------------------------------------------------------------
// Kernel 2: combined coefficients (fp16, planar SoA [tap][b][y][x])
// ---------------------------------------------------------------------------
__global__ void __launch_bounds__(256) compute_weights(const float* __restrict__ image,
                                                       const float* __restrict__ edges) {
    __shared__ float sg[4][12][36];
    int tx = threadIdx.x, ty = threadIdx.y;
    int b = blockIdx.z;
    int x0 = blockIdx.x * 32, y0 = blockIdx.y * 8;
    int tid = ty * 32 + tx;

    for (int idx = tid; idx < 4*12*36; idx += 256) {
        int ch = idx / (12*36);
        int r  = idx % (12*36);
        int ry = r / 36, sx = r % 36;
        int gy = reflect_idx(y0 + ry - 2, H);
        int gx = reflect_idx(x0 + sx - 2, W);
        float v;
        if (ch < 3) v = image[((size_t)(b*3 + ch))*HW + gy*W + gx];
        else        v = edges[(size_t)b*HW + gy*W + gx];
        sg[ch][ry][sx] = v;
    }
    __syncthreads();

    float sp[5], g2[5];
    {
        float s = 0.f;
#pragma unroll
        for (int i = 0; i < 5; i++) {
            float x = (float)(i - 2);
            sp[i] = __expf(-x*x * 0.02f);
            float g = __expf(-2.f * x*x);
            g2[i] = g; s += g;
        }
        float inv = 1.f / s;
#pragma unroll
        for (int i = 0; i < 5; i++) g2[i] *= inv;
    }

    int ry = ty + 2, rx = tx + 2;
    float cr = sg[0][ry][rx], cg = sg[1][ry][rx], cb = sg[2][ry][rx], ce = sg[3][ry][rx];

    float wr[NTAP], we[NTAP];
    float sr = 0.f, se = 0.f;
#pragma unroll
    for (int dy = 0; dy < 5; dy++) {
#pragma unroll
        for (int dx = 0; dx < 5; dx++) {
            int t = dy*5 + dx;
            float d = fabsf(sg[0][ry+dy-2][rx+dx-2] - cr)
                    + fabsf(sg[1][ry+dy-2][rx+dx-2] - cg)
                    + fabsf(sg[2][ry+dy-2][rx+dx-2] - cb);
            float s2 = sp[dy] * sp[dx];
            float w  = s2 * __expf(-2.f * d * d);
            wr[t] = w; sr += w;
            float de = fabsf(sg[3][ry+dy-2][rx+dx-2] - ce);
            float w2 = s2 * __expf(-2.f * de * de);
            we[t] = w2; se += w2;
        }
    }
    float isr = 1.f / sr, ise = 1.f / se;
    int pix = b*HW + (y0 + ty)*W + (x0 + tx);
#pragma unroll
    for (int dy = 0; dy < 5; dy++) {
#pragma unroll
        for (int dx = 0; dx < 5; dx++) {
            int t = dy*5 + dx;
            g_wch[t*(NB*HW) + pix] = __float2half(g2[dy]*g2[dx] + wr[t]*isr + we[t]*ise);
        }
    }
}

// ---------------------------------------------------------------------------
// Kernel 3: one CRF iteration, pair-planar (R12 + coef software pipelining).
// Tile 64x8, block (32,8)=256 thr, 2 px/thread, 3 CTAs/SM.
// smem [row 12][cc 11][px 68][2] fp32; inner 3xLDS.128 + 10xFFMA2.
// Coef fp16 LDGs pipelined: dy0 issued under the cp.async drain, dy+1 issued
// before dy's cc loop so the FMA block hides their latency.
// ---------------------------------------------------------------------------
#define TX 64
#define TY 8
#define SWPX 68
#define SH 12
#define PLB 544          // bytes per (row,cc) plane = 68*8
#define RPB (NCC*PLB)    // 5984 bytes per smem row
#define NCHK (SH*NCC*34) // 4488 16B chunks

template<bool FINAL>
__global__ void __launch_bounds__(256, 3) crf_iter(const float* __restrict__ unary,
                                                   const float* __restrict__ qin,
                                                   float* __restrict__ qout,
                                                   float* __restrict__ outp) {
    __shared__ float sq[SH*NCC*SWPX*2];   // 71808 B
    int tx = threadIdx.x, ty = threadIdx.y;
    int b = blockIdx.z;
    int x0 = blockIdx.x * TX, y0 = blockIdx.y * TY;
    int tid = ty * 32 + tx;
    int lastbx = (int)gridDim.x - 1;
    bool bx0 = (blockIdx.x == 0), bxL = (blockIdx.x == lastbx);

    const float* qb = qin + (size_t)b * H * NCC * (W*2);
    uint32_t sbase = (uint32_t)__cvta_generic_to_shared(sq);

    // ---- fill: all 256 threads, chunk idx = (row, cc, cx), incremental ----
    {
        int idx = tid;
        int cx  = tid % 34;
        int pl  = tid / 34;
        int cc  = pl % NCC;
        int row = pl / NCC;
#pragma unroll
        for (int it = 0; it < 18; it++) {
            if (idx < NCHK) {
                bool skip = (bx0 && cx == 0) || (bxL && cx == 33);
                if (!skip) {
                    int gy = reflect_idx(y0 + row - 2, H);
                    const float* src = qb + ((size_t)gy*NCC + cc)*(W*2)
                                     + (x0 - 2)*2 + cx*4;
                    uint32_t dst = sbase + (uint32_t)(row*RPB + cc*PLB + cx*16);
                    asm volatile("cp.async.cg.shared.global [%0], [%1], 16;"
                                 :: "r"(dst), "l"(src));
                }
            }
            idx += 256;
            cx += 18; int cinc = 7;
            if (cx >= 34) { cx -= 34; cinc = 8; }
            cc += cinc;
            if (cc >= NCC) { cc -= NCC; row++; }
        }
        asm volatile("cp.async.commit_group;");
    }

    int px0 = x0 + 2*tx;
    int gy  = y0 + ty;
    int wbase = b*HW + gy*W + px0;
    const __half* wpbase = g_wch + wbase;

    // dy0 coef loads issued while the cp.async fill drains
    uint32_t raw[5];
#pragma unroll
    for (int k = 0; k < 5; k++)
        raw[k] = *reinterpret_cast<const uint32_t*>(wpbase + (size_t)k*NBHW);

    // boundary reflect fix-ups (also overlap the fill drain)
    if ((bx0 || bxL) && tid < SH*NCC) {
        int row = tid / NCC, cc = tid % NCC;
        int gyr = reflect_idx(y0 + row - 2, H);
        const float* pl = qb + ((size_t)gyr*NCC + cc)*(W*2);
        char* base = reinterpret_cast<char*>(sq) + row*RPB + cc*PLB;
        if (bx0) {
            float2 v0 = *reinterpret_cast<const float2*>(pl + 2*2);
            float2 v1 = *reinterpret_cast<const float2*>(pl + 1*2);
            *reinterpret_cast<float2*>(base)     = v0;
            *reinterpret_cast<float2*>(base + 8) = v1;
        }
        if (bxL) {
            float2 v0 = *reinterpret_cast<const float2*>(pl + 510*2);
            float2 v1 = *reinterpret_cast<const float2*>(pl + 509*2);
            *reinterpret_cast<float2*>(base + 66*8) = v0;
            *reinterpret_cast<float2*>(base + 67*8) = v1;
        }
    }
    asm volatile("cp.async.wait_group 0;" ::: "memory");
    __syncthreads();

    unsigned long long acc0[NCC], acc1[NCC];
#pragma unroll
    for (int cc = 0; cc < NCC; cc++) { acc0[cc] = 0ULL; acc1[cc] = 0ULL; }

    const char* sb = reinterpret_cast<const char*>(sq);

#pragma unroll
    for (int dy = 0; dy < 5; dy++) {
        // convert current raw coefs -> broadcast fp32x2 pairs
        float2 c0 = __half22float2(*reinterpret_cast<__half2*>(&raw[0]));
        float2 c1 = __half22float2(*reinterpret_cast<__half2*>(&raw[1]));
        float2 c2 = __half22float2(*reinterpret_cast<__half2*>(&raw[2]));
        float2 c3 = __half22float2(*reinterpret_cast<__half2*>(&raw[3]));
        float2 c4 = __half22float2(*reinterpret_cast<__half2*>(&raw[4]));
        unsigned long long CC00 = pk2(c0.x, c0.x), CC10 = pk2(c0.y, c0.y);
        unsigned long long CC01 = pk2(c1.x, c1.x), CC11 = pk2(c1.y, c1.y);
        unsigned long long CC02 = pk2(c2.x, c2.x), CC12 = pk2(c2.y, c2.y);
        unsigned long long CC03 = pk2(c3.x, c3.x), CC13 = pk2(c3.y, c3.y);
        unsigned long long CC04 = pk2(c4.x, c4.x), CC14 = pk2(c4.y, c4.y);

        // issue NEXT dy's coef loads — latency hidden behind this dy's cc loop
        if (dy < 4) {
            const __half* wpn = wpbase + (size_t)((dy + 1)*5)*NBHW;
#pragma unroll
            for (int k = 0; k < 5; k++)
                raw[k] = *reinterpret_cast<const uint32_t*>(wpn + (size_t)k*NBHW);
        }

        const char* rb = sb + (ty + dy)*RPB + tx*16;   // window cols 2tx..2tx+5
#pragma unroll
        for (int cc = 0; cc < NCC; cc++) {
            const char* a = rb + cc*PLB;
            ulonglong2 w01 = *reinterpret_cast<const ulonglong2*>(a);       // cols 0,1
            ulonglong2 w23 = *reinterpret_cast<const ulonglong2*>(a + 16);  // cols 2,3
            ulonglong2 w45 = *reinterpret_cast<const ulonglong2*>(a + 32);  // cols 4,5
            FMA2(acc0[cc], CC00, w01.x);
            FMA2(acc0[cc], CC01, w01.y);
            FMA2(acc0[cc], CC02, w23.x);
            FMA2(acc0[cc], CC03, w23.y);
            FMA2(acc0[cc], CC04, w45.x);
            FMA2(acc1[cc], CC10, w01.y);
            FMA2(acc1[cc], CC11, w23.x);
            FMA2(acc1[cc], CC12, w23.y);
            FMA2(acc1[cc], CC13, w45.x);
            FMA2(acc1[cc], CC14, w45.y);
        }
    }

    // ---- epilogue: q = softmax(unary - F) ----
    const float* ub = unary + (size_t)b * NC * HW + gy*W + px0;
    float s0 = 0.f, s1 = 0.f;
#pragma unroll
    for (int cc = 0; cc < NCC; cc++) {
        float fa, fb, ga, gb;
        upk2(fa, fb, acc0[cc]);   // px0: ch 2cc, 2cc+1
        upk2(ga, gb, acc1[cc]);   // px1
        float2 uA = *reinterpret_cast<const float2*>(ub + (size_t)(2*cc)*HW);
        float e00 = __expf(uA.x - fa);
        float e10 = __expf(uA.y - ga);
        float e01 = 0.f, e11 = 0.f;
        if (cc < 10) {
            float2 uB = *reinterpret_cast<const float2*>(ub + (size_t)(2*cc+1)*HW);
            e01 = __expf(uB.x - fb);
            e11 = __expf(uB.y - gb);
        }
        acc0[cc] = pk2(e00, e01);
        acc1[cc] = pk2(e10, e11);
        s0 += e00 + e01;
        s1 += e10 + e11;
    }
    float i0 = 1.f / s0, i1 = 1.f / s1;

    if (FINAL) {
        float* op = outp + (size_t)b * NC * HW + gy*W + px0;
#pragma unroll
        for (int cc = 0; cc < NCC; cc++) {
            float e00, e01, e10, e11;
            upk2(e00, e01, acc0[cc]);
            upk2(e10, e11, acc1[cc]);
            float2 vA; vA.x = e00*i0; vA.y = e10*i1;
            *reinterpret_cast<float2*>(op + (size_t)(2*cc)*HW) = vA;
            if (cc < 10) {
                float2 vB; vB.x = e01*i0; vB.y = e11*i1;
                *reinterpret_cast<float2*>(op + (size_t)(2*cc+1)*HW) = vB;
            }
        }
    } else {
        unsigned long long I0 = pk2(i0, i0), I1 = pk2(i1, i1);
        float* qo = qout + (size_t)b * H * NCC * (W*2)
                         + ((size_t)gy*NCC)*(W*2) + px0*2;
#pragma unroll
        for (int cc = 0; cc < NCC; cc++) {
            ulonglong2 st;
            MUL2(st.x, acc0[cc], I0);   // px0 pair
            MUL2(st.y, acc1[cc], I1);   // px1 pair
            *reinterpret_cast<ulonglong2*>(qo + cc*(W*2)) = st;
        }
    }
}

// ---------------------------------------------------------------------------
extern "C" void kernel_launch(void* const* d_in, const int* in_sizes, int n_in,
                              void* d_out, int out_size) {
    const float *unary = nullptr, *image = nullptr, *edges = nullptr;
    for (int i = 0; i < n_in; i++) {
        if      (in_sizes[i] == NB*NC*HW) unary = (const float*)d_in[i];
        else if (in_sizes[i] == NB*3*HW)  image = (const float*)d_in[i];
        else if (in_sizes[i] == NB*HW)    edges = (const float*)d_in[i];
    }
    float* out = (float*)d_out;

    float *qA = nullptr, *qB = nullptr;
    cudaGetSymbolAddress((void**)&qA, g_qA);
    cudaGetSymbolAddress((void**)&qB, g_qB);

    init_softmax<<<(NPIX + 255)/256, 256>>>(unary, qA);
    compute_weights<<<dim3(W/32, H/8, NB), dim3(32, 8)>>>(image, edges);

    dim3 gi(W/TX, H/TY, NB), bi(32, 8);
    const float* cur = qA;
    for (int it = 0; it < 9; it++) {
        float* dst = (cur == qA) ? qB : qA;
        crf_iter<false><<<gi, bi>>>(unary, cur, dst, nullptr);
        cur = dst;
    }
    crf_iter<true><<<gi, bi>>>(unary, cur, nullptr, out);
}